// round 2
// baseline (speedup 1.0000x reference)
#include <cuda_runtime.h>
#include <mma.h>
using namespace nvcuda;

#define B_   2
#define S_   2048
#define H_   1024
#define NH_  16
#define DH_  64
#define RV_  4096
#define BH_  (B_*NH_)     // 32

// Scratch (allocation-free rule: __device__ globals)
__device__ float g_q[(size_t)BH_*S_*DH_];
__device__ float g_k[(size_t)BH_*S_*DH_];
__device__ float g_v[(size_t)BH_*S_*DH_];
__device__ float g_sc[(size_t)BH_*S_*S_];   // 512 MB scores/probs

// ---------------------------------------------------------------------------
// Kernel 1: fused QKV projection. out = hidden @ W^T + bias, split to heads.
// M=4096 (b,s), N=1024 (h,d), K=1024. blockIdx.z selects Q/K/V.
// TF32 WMMA, 128x128 block tile, BK=32, 8 warps (2x4), warp tile 64x32.
// ---------------------------------------------------------------------------
__global__ void __launch_bounds__(256) qkv_kernel(
    const float* __restrict__ hidden,
    const float* __restrict__ Wq, const float* __restrict__ bq,
    const float* __restrict__ Wk, const float* __restrict__ bk,
    const float* __restrict__ Wv, const float* __restrict__ bv)
{
    const float* W; const float* bias; float* outp;
    if (blockIdx.z == 0)      { W = Wq; bias = bq; outp = g_q; }
    else if (blockIdx.z == 1) { W = Wk; bias = bk; outp = g_k; }
    else                      { W = Wv; bias = bv; outp = g_v; }

    __shared__ float As[128][36];
    __shared__ float Bs[128][36];
    __shared__ float biasSm[16][132];

    const int tid = threadIdx.x;
    const int wid = tid >> 5;
    const int m0 = blockIdx.y * 128;
    const int n0 = blockIdx.x * 128;
    const int warpM = wid >> 2;     // 0..1
    const int warpN = wid & 3;      // 0..3

    // Replicated bias tile (16 identical rows) so accumulators init via load.
    for (int j = tid; j < 128; j += 256) {
        float bv_ = bias[n0 + j];
        #pragma unroll
        for (int r = 0; r < 16; r++) biasSm[r][j] = bv_;
    }
    __syncthreads();

    wmma::fragment<wmma::accumulator, 16, 16, 8, float> acc[4][2];
    #pragma unroll
    for (int i = 0; i < 4; i++)
        #pragma unroll
        for (int j = 0; j < 2; j++)
            wmma::load_matrix_sync(acc[i][j], &biasSm[0][warpN*32 + j*16], 132,
                                   wmma::mem_row_major);

    const int lr = tid >> 3;        // 0..31
    const int lc = (tid & 7) * 4;   // 0..28

    for (int kt = 0; kt < 1024; kt += 32) {
        __syncthreads();
        #pragma unroll
        for (int p = 0; p < 4; p++) {
            int r = p*32 + lr;
            *(float4*)&As[r][lc] =
                *(const float4*)(hidden + (size_t)(m0 + r)*1024 + kt + lc);
            *(float4*)&Bs[r][lc] =
                *(const float4*)(W + (size_t)(n0 + r)*1024 + kt + lc);
        }
        __syncthreads();
        #pragma unroll
        for (int ks = 0; ks < 32; ks += 8) {
            wmma::fragment<wmma::matrix_a, 16, 16, 8, wmma::precision::tf32,
                           wmma::row_major> af[4];
            wmma::fragment<wmma::matrix_b, 16, 16, 8, wmma::precision::tf32,
                           wmma::col_major> bf[2];
            #pragma unroll
            for (int i = 0; i < 4; i++) {
                wmma::load_matrix_sync(af[i], &As[warpM*64 + i*16][ks], 36);
                #pragma unroll
                for (int t = 0; t < af[i].num_elements; t++)
                    af[i].x[t] = wmma::__float_to_tf32(af[i].x[t]);
            }
            #pragma unroll
            for (int j = 0; j < 2; j++) {
                wmma::load_matrix_sync(bf[j], &Bs[warpN*32 + j*16][ks], 36);
                #pragma unroll
                for (int t = 0; t < bf[j].num_elements; t++)
                    bf[j].x[t] = wmma::__float_to_tf32(bf[j].x[t]);
            }
            #pragma unroll
            for (int i = 0; i < 4; i++)
                #pragma unroll
                for (int j = 0; j < 2; j++)
                    wmma::mma_sync(acc[i][j], af[i], bf[j], acc[i][j]);
        }
    }

    // Store to [b, h, s, d] (fragment n-span of 16, aligned, never crosses a head)
    const int b  = m0 / S_;
    const int s0 = m0 % S_;
    #pragma unroll
    for (int i = 0; i < 4; i++) {
        int sm = s0 + warpM*64 + i*16;
        #pragma unroll
        for (int j = 0; j < 2; j++) {
            int n = n0 + warpN*32 + j*16;
            int h = n >> 6, d = n & 63;
            float* dst = outp + ((size_t)(b*NH_ + h)*S_ + sm)*DH_ + d;
            wmma::store_matrix_sync(dst, acc[i][j], DH_, wmma::mem_row_major);
        }
    }
}

// ---------------------------------------------------------------------------
// Kernel 2: raw scores = Q @ K^T (no scale/bias yet — applied in softmax).
// Per (b,h): M=2048, N=2048, K=64. 128x128 tile, BK=32, 8 warps (2x4).
// ---------------------------------------------------------------------------
__global__ void __launch_bounds__(256) scores_kernel()
{
    __shared__ float As[128][36];
    __shared__ float Bs[128][36];

    const int tid = threadIdx.x;
    const int wid = tid >> 5;
    const int bh = blockIdx.z;
    const float* Q = g_q + (size_t)bh*S_*DH_;
    const float* K = g_k + (size_t)bh*S_*DH_;
    float* SC = g_sc + (size_t)bh*S_*S_;

    const int q0 = blockIdx.y * 128;
    const int k0 = blockIdx.x * 128;
    const int warpM = wid >> 2;
    const int warpN = wid & 3;

    wmma::fragment<wmma::accumulator, 16, 16, 8, float> acc[4][2];
    #pragma unroll
    for (int i = 0; i < 4; i++)
        #pragma unroll
        for (int j = 0; j < 2; j++)
            wmma::fill_fragment(acc[i][j], 0.0f);

    const int lr = tid >> 3;
    const int lc = (tid & 7) * 4;

    #pragma unroll
    for (int kt = 0; kt < 64; kt += 32) {
        __syncthreads();
        #pragma unroll
        for (int p = 0; p < 4; p++) {
            int r = p*32 + lr;
            *(float4*)&As[r][lc] =
                *(const float4*)(Q + (size_t)(q0 + r)*DH_ + kt + lc);
            *(float4*)&Bs[r][lc] =
                *(const float4*)(K + (size_t)(k0 + r)*DH_ + kt + lc);
        }
        __syncthreads();
        #pragma unroll
        for (int ks = 0; ks < 32; ks += 8) {
            wmma::fragment<wmma::matrix_a, 16, 16, 8, wmma::precision::tf32,
                           wmma::row_major> af[4];
            wmma::fragment<wmma::matrix_b, 16, 16, 8, wmma::precision::tf32,
                           wmma::col_major> bf[2];
            #pragma unroll
            for (int i = 0; i < 4; i++) {
                wmma::load_matrix_sync(af[i], &As[warpM*64 + i*16][ks], 36);
                #pragma unroll
                for (int t = 0; t < af[i].num_elements; t++)
                    af[i].x[t] = wmma::__float_to_tf32(af[i].x[t]);
            }
            #pragma unroll
            for (int j = 0; j < 2; j++) {
                wmma::load_matrix_sync(bf[j], &Bs[warpN*32 + j*16][ks], 36);
                #pragma unroll
                for (int t = 0; t < bf[j].num_elements; t++)
                    bf[j].x[t] = wmma::__float_to_tf32(bf[j].x[t]);
            }
            #pragma unroll
            for (int i = 0; i < 4; i++)
                #pragma unroll
                for (int j = 0; j < 2; j++)
                    wmma::mma_sync(acc[i][j], af[i], bf[j], acc[i][j]);
        }
    }

    #pragma unroll
    for (int i = 0; i < 4; i++)
        #pragma unroll
        for (int j = 0; j < 2; j++) {
            float* dst = SC + (size_t)(q0 + warpM*64 + i*16)*S_
                            + (k0 + warpN*32 + j*16);
            wmma::store_matrix_sync(dst, acc[i][j], S_, wmma::mem_row_major);
        }
}

// ---------------------------------------------------------------------------
// Kernel 3: softmax with fused epilogue:
//   x = score/8 + dist_emb[distance_idx[q,k]][h] + mask[b,k]; softmax over k.
// One warp per q-row (64 elems/lane); dist_emb[:,h] staged in smem (16 KB).
// ---------------------------------------------------------------------------
__global__ void __launch_bounds__(256) softmax_kernel(
    const int* __restrict__ dist_idx,
    const float* __restrict__ dist_emb,
    const float* __restrict__ mask)
{
    __shared__ float distCol[RV_];
    const int bh = blockIdx.y;
    const int h = bh & (NH_ - 1);
    const int b = bh >> 4;
    const int tid = threadIdx.x;

    for (int i = tid; i < RV_; i += 256)
        distCol[i] = dist_emb[(size_t)i*NH_ + h];
    __syncthreads();

    const int wid = tid >> 5, lane = tid & 31;
    const int q = blockIdx.x * 8 + wid;
    float* row = g_sc + ((size_t)bh*S_ + q)*S_;
    const int* drow = dist_idx + (size_t)q*S_;
    const float* mrow = mask + (size_t)b*S_;

    float vals[64];
    float mx = -1e30f;
    #pragma unroll
    for (int i = 0; i < 64; i++) {
        int k = i*32 + lane;
        float v = row[k]*0.125f + distCol[drow[k]] + mrow[k];
        vals[i] = v;
        mx = fmaxf(mx, v);
    }
    #pragma unroll
    for (int o = 16; o; o >>= 1) mx = fmaxf(mx, __shfl_xor_sync(0xffffffffu, mx, o));

    float sum = 0.0f;
    #pragma unroll
    for (int i = 0; i < 64; i++) {
        float e = __expf(vals[i] - mx);
        vals[i] = e;
        sum += e;
    }
    #pragma unroll
    for (int o = 16; o; o >>= 1) sum += __shfl_xor_sync(0xffffffffu, sum, o);
    const float inv = 1.0f / sum;

    #pragma unroll
    for (int i = 0; i < 64; i++)
        row[i*32 + lane] = vals[i] * inv;
}

// ---------------------------------------------------------------------------
// Kernel 4: ctx = probs @ V, written directly in [B, S, H] output layout.
// Per (b,h): M=2048, N=64, K=2048. 128x64 tile, BK=32, 8 warps (4x2).
// ---------------------------------------------------------------------------
__global__ void __launch_bounds__(256) pv_kernel(float* __restrict__ out)
{
    __shared__ float Ps[128][36];
    __shared__ float Vs[32][72];

    const int tid = threadIdx.x;
    const int wid = tid >> 5;
    const int bh = blockIdx.y;
    const int b = bh >> 4, h = bh & (NH_ - 1);
    const float* P = g_sc + (size_t)bh*S_*S_;
    const float* V = g_v + (size_t)bh*S_*DH_;
    const int q0 = blockIdx.x * 128;
    const int warpM = wid >> 1;     // 0..3, m offset 32*warpM
    const int warpN = wid & 1;      // 0..1, n offset 32*warpN

    wmma::fragment<wmma::accumulator, 16, 16, 8, float> acc[2][2];
    #pragma unroll
    for (int i = 0; i < 2; i++)
        #pragma unroll
        for (int j = 0; j < 2; j++)
            wmma::fill_fragment(acc[i][j], 0.0f);

    const int lr = tid >> 3;          // Ps: 32 rows/pass
    const int lc = (tid & 7) * 4;
    const int vr = tid >> 4;          // Vs: 16 rows/pass
    const int vc = (tid & 15) * 4;

    for (int kt = 0; kt < S_; kt += 32) {
        __syncthreads();
        #pragma unroll
        for (int p = 0; p < 4; p++) {
            int r = p*32 + lr;
            *(float4*)&Ps[r][lc] =
                *(const float4*)(P + (size_t)(q0 + r)*S_ + kt + lc);
        }
        #pragma unroll
        for (int p = 0; p < 2; p++) {
            int r = p*16 + vr;
            *(float4*)&Vs[r][vc] =
                *(const float4*)(V + (size_t)(kt + r)*DH_ + vc);
        }
        __syncthreads();
        #pragma unroll
        for (int ks = 0; ks < 32; ks += 8) {
            wmma::fragment<wmma::matrix_a, 16, 16, 8, wmma::precision::tf32,
                           wmma::row_major> af[2];
            wmma::fragment<wmma::matrix_b, 16, 16, 8, wmma::precision::tf32,
                           wmma::row_major> bf[2];
            #pragma unroll
            for (int i = 0; i < 2; i++) {
                wmma::load_matrix_sync(af[i], &Ps[warpM*32 + i*16][ks], 36);
                #pragma unroll
                for (int t = 0; t < af[i].num_elements; t++)
                    af[i].x[t] = wmma::__float_to_tf32(af[i].x[t]);
            }
            #pragma unroll
            for (int j = 0; j < 2; j++) {
                wmma::load_matrix_sync(bf[j], &Vs[ks][warpN*32 + j*16], 72);
                #pragma unroll
                for (int t = 0; t < bf[j].num_elements; t++)
                    bf[j].x[t] = wmma::__float_to_tf32(bf[j].x[t]);
            }
            #pragma unroll
            for (int i = 0; i < 2; i++)
                #pragma unroll
                for (int j = 0; j < 2; j++)
                    wmma::mma_sync(acc[i][j], af[i], bf[j], acc[i][j]);
        }
    }

    #pragma unroll
    for (int i = 0; i < 2; i++) {
        int s = q0 + warpM*32 + i*16;
        #pragma unroll
        for (int j = 0; j < 2; j++) {
            int d = warpN*32 + j*16;
            float* dst = out + ((size_t)(b*S_ + s))*H_ + h*DH_ + d;
            wmma::store_matrix_sync(dst, acc[i][j], H_, wmma::mem_row_major);
        }
    }
}

// ---------------------------------------------------------------------------
// Launch. Inputs (metadata order): hidden, attention_mask, distance_idx,
// Wq, bq, Wk, bk, Wv, bv, dist_emb. Output: float32 [B,S,H].
// ---------------------------------------------------------------------------
extern "C" void kernel_launch(void* const* d_in, const int* in_sizes, int n_in,
                              void* d_out, int out_size)
{
    const float* hidden   = (const float*)d_in[0];
    const float* mask     = (const float*)d_in[1];
    const int*   dist_idx = (const int*)  d_in[2];
    const float* Wq       = (const float*)d_in[3];
    const float* bq       = (const float*)d_in[4];
    const float* Wk       = (const float*)d_in[5];
    const float* bk       = (const float*)d_in[6];
    const float* Wv       = (const float*)d_in[7];
    const float* bv       = (const float*)d_in[8];
    const float* dist_emb = (const float*)d_in[9];
    float* out = (float*)d_out;

    qkv_kernel<<<dim3(H_/128, (B_*S_)/128, 3), 256>>>(hidden, Wq, bq, Wk, bk, Wv, bv);
    scores_kernel<<<dim3(S_/128, S_/128, BH_), 256>>>();
    softmax_kernel<<<dim3(S_/8, BH_), 256>>>(dist_idx, dist_emb, mask);
    pv_kernel<<<dim3(S_/128, BH_), 256>>>(out);
}

// round 5
// speedup vs baseline: 1.2995x; 1.2995x over previous
#include <cuda_runtime.h>
#include <mma.h>
#include <cstdint>
using namespace nvcuda;

#define B_   2
#define S_   2048
#define H_   1024
#define NH_  16
#define DH_  64
#define RV_  4096
#define BH_  (B_*NH_)     // 32

// Scratch (allocation-free rule: __device__ globals)
__device__ float g_q[(size_t)BH_*S_*DH_];
__device__ float g_k[(size_t)BH_*S_*DH_];
__device__ float g_v[(size_t)BH_*S_*DH_];

// ---------------------------------------------------------------------------
// Kernel 1: fused QKV projection (unchanged from round 1).
// ---------------------------------------------------------------------------
__global__ void __launch_bounds__(256) qkv_kernel(
    const float* __restrict__ hidden,
    const float* __restrict__ Wq, const float* __restrict__ bq,
    const float* __restrict__ Wk, const float* __restrict__ bk,
    const float* __restrict__ Wv, const float* __restrict__ bv)
{
    const float* W; const float* bias; float* outp;
    if (blockIdx.z == 0)      { W = Wq; bias = bq; outp = g_q; }
    else if (blockIdx.z == 1) { W = Wk; bias = bk; outp = g_k; }
    else                      { W = Wv; bias = bv; outp = g_v; }

    __shared__ float As[128][36];
    __shared__ float Bs[128][36];
    __shared__ float biasSm[16][132];

    const int tid = threadIdx.x;
    const int wid = tid >> 5;
    const int m0 = blockIdx.y * 128;
    const int n0 = blockIdx.x * 128;
    const int warpM = wid >> 2;
    const int warpN = wid & 3;

    for (int j = tid; j < 128; j += 256) {
        float bv_ = bias[n0 + j];
        #pragma unroll
        for (int r = 0; r < 16; r++) biasSm[r][j] = bv_;
    }
    __syncthreads();

    wmma::fragment<wmma::accumulator, 16, 16, 8, float> acc[4][2];
    #pragma unroll
    for (int i = 0; i < 4; i++)
        #pragma unroll
        for (int j = 0; j < 2; j++)
            wmma::load_matrix_sync(acc[i][j], &biasSm[0][warpN*32 + j*16], 132,
                                   wmma::mem_row_major);

    const int lr = tid >> 3;
    const int lc = (tid & 7) * 4;

    for (int kt = 0; kt < 1024; kt += 32) {
        __syncthreads();
        #pragma unroll
        for (int p = 0; p < 4; p++) {
            int r = p*32 + lr;
            *(float4*)&As[r][lc] =
                *(const float4*)(hidden + (size_t)(m0 + r)*1024 + kt + lc);
            *(float4*)&Bs[r][lc] =
                *(const float4*)(W + (size_t)(n0 + r)*1024 + kt + lc);
        }
        __syncthreads();
        #pragma unroll
        for (int ks = 0; ks < 32; ks += 8) {
            wmma::fragment<wmma::matrix_a, 16, 16, 8, wmma::precision::tf32,
                           wmma::row_major> af[4];
            wmma::fragment<wmma::matrix_b, 16, 16, 8, wmma::precision::tf32,
                           wmma::col_major> bf[2];
            #pragma unroll
            for (int i = 0; i < 4; i++) {
                wmma::load_matrix_sync(af[i], &As[warpM*64 + i*16][ks], 36);
                #pragma unroll
                for (int t = 0; t < af[i].num_elements; t++)
                    af[i].x[t] = wmma::__float_to_tf32(af[i].x[t]);
            }
            #pragma unroll
            for (int j = 0; j < 2; j++) {
                wmma::load_matrix_sync(bf[j], &Bs[warpN*32 + j*16][ks], 36);
                #pragma unroll
                for (int t = 0; t < bf[j].num_elements; t++)
                    bf[j].x[t] = wmma::__float_to_tf32(bf[j].x[t]);
            }
            #pragma unroll
            for (int i = 0; i < 4; i++)
                #pragma unroll
                for (int j = 0; j < 2; j++)
                    wmma::mma_sync(acc[i][j], af[i], bf[j], acc[i][j]);
        }
    }

    const int b  = m0 / S_;
    const int s0 = m0 % S_;
    #pragma unroll
    for (int i = 0; i < 4; i++) {
        int sm = s0 + warpM*64 + i*16;
        #pragma unroll
        for (int j = 0; j < 2; j++) {
            int n = n0 + warpN*32 + j*16;
            int h = n >> 6, d = n & 63;
            float* dst = outp + ((size_t)(b*NH_ + h)*S_ + sm)*DH_ + d;
            wmma::store_matrix_sync(dst, acc[i][j], DH_, wmma::mem_row_major);
        }
    }
}

// ---------------------------------------------------------------------------
// Kernel 2: fused flash attention with relative-position bias.
//   Per block: (b,h), 128 q-rows. Online softmax over 16 k-tiles of 128.
//   Raw mma.sync.m16n8k8 tf32 (documented fragment layout: thread owns rows
//   lane>>2 and lane>>2+8). 8 warps, each owns 16 q-rows x full tile.
//   All mma operands pre-converted to tf32 at smem store.
// ---------------------------------------------------------------------------
struct FlashSmem {
    float distCol[RV_];        // dist_emb[:,h]            16 KB
    float msk[S_];             // mask[b,:]                 8 KB
    uint32_t Ks[128][68];      // K tile, tf32 bits        34 KB (pad: conflict-free frags)
    uint32_t Vt[64][132];      // V tile transposed, tf32  33 KB
    uint32_t Ps[128][132];     // P = exp(S-m), tf32       66 KB
};

__device__ __forceinline__ uint32_t f2tf(float f) {
    uint32_t u; asm("cvt.rna.tf32.f32 %0, %1;" : "=r"(u) : "f"(f)); return u;
}
__device__ __forceinline__ void mma8(float* d, const uint32_t* a,
                                     uint32_t b0, uint32_t b1) {
    asm volatile("mma.sync.aligned.m16n8k8.row.col.f32.tf32.tf32.f32 "
        "{%0,%1,%2,%3}, {%4,%5,%6,%7}, {%8,%9}, {%0,%1,%2,%3};"
        : "+f"(d[0]), "+f"(d[1]), "+f"(d[2]), "+f"(d[3])
        : "r"(a[0]), "r"(a[1]), "r"(a[2]), "r"(a[3]), "r"(b0), "r"(b1));
}

__global__ void __launch_bounds__(256, 1) flash_kernel(
    const int* __restrict__ dist_idx,
    const float* __restrict__ dist_emb,
    const float* __restrict__ mask,
    float* __restrict__ out)
{
    extern __shared__ char smraw[];
    FlashSmem& sm = *reinterpret_cast<FlashSmem*>(smraw);

    const int tid = threadIdx.x, wid = tid >> 5, lane = tid & 31;
    const int r0 = lane >> 2, c0 = lane & 3;
    const int bh = blockIdx.y, b = bh >> 4, h = bh & 15;
    const int q0 = blockIdx.x * 128;

    for (int i = tid; i < RV_; i += 256)
        sm.distCol[i] = dist_emb[(size_t)i*NH_ + h];
    for (int i = tid; i < S_; i += 256)
        sm.msk[i] = mask[b*S_ + i];

    const float* Qp = g_q + (size_t)bh*S_*DH_;
    const float* Kp = g_k + (size_t)bh*S_*DH_;
    const float* Vp = g_v + (size_t)bh*S_*DH_;

    const int qA = q0 + wid*16 + r0;     // this thread's two q-rows
    const int qB = qA + 8;

    // Persistent Q A-fragments, pre-scaled by 1/sqrt(64) and tf32-converted.
    uint32_t aQ[8][4];
    #pragma unroll
    for (int kf = 0; kf < 8; kf++) {
        aQ[kf][0] = f2tf(Qp[(size_t)qA*DH_ + kf*8 + c0]     * 0.125f);
        aQ[kf][1] = f2tf(Qp[(size_t)qB*DH_ + kf*8 + c0]     * 0.125f);
        aQ[kf][2] = f2tf(Qp[(size_t)qA*DH_ + kf*8 + c0 + 4] * 0.125f);
        aQ[kf][3] = f2tf(Qp[(size_t)qB*DH_ + kf*8 + c0 + 4] * 0.125f);
    }

    float mA = -1e30f, mB = -1e30f, lA = 0.f, lB = 0.f;
    float O[8][4];
    #pragma unroll
    for (int jn = 0; jn < 8; jn++)
        O[jn][0] = O[jn][1] = O[jn][2] = O[jn][3] = 0.f;

    const int krow = tid >> 1;           // K/V tile load mapping
    const int dhalf = (tid & 1) * 32;
    const int prA = wid*16 + r0, prB = prA + 8;   // P smem rows

    for (int kt = 0; kt < 16; kt++) {
        const int k0 = kt * 128;
        __syncthreads();   // protect K/V/P reuse across iterations

        // Stage K (tf32) and V (transposed, tf32)
        #pragma unroll
        for (int i = 0; i < 8; i++) {
            int d = dhalf + i*4;
            float4 kv = *(const float4*)(Kp + (size_t)(k0 + krow)*DH_ + d);
            uint4 ku = make_uint4(f2tf(kv.x), f2tf(kv.y), f2tf(kv.z), f2tf(kv.w));
            *(uint4*)&sm.Ks[krow][d] = ku;
            float4 vv = *(const float4*)(Vp + (size_t)(k0 + krow)*DH_ + d);
            sm.Vt[d+0][krow] = f2tf(vv.x);
            sm.Vt[d+1][krow] = f2tf(vv.y);
            sm.Vt[d+2][krow] = f2tf(vv.z);
            sm.Vt[d+3][krow] = f2tf(vv.w);
        }
        __syncthreads();

        // S = Q K^T for this warp's 16 rows x 128 cols
        float Sv[16][4];
        #pragma unroll
        for (int j = 0; j < 16; j++) {
            Sv[j][0] = Sv[j][1] = Sv[j][2] = Sv[j][3] = 0.f;
            #pragma unroll
            for (int kf = 0; kf < 8; kf++) {
                uint32_t b0 = sm.Ks[j*8 + r0][kf*8 + c0];
                uint32_t b1 = sm.Ks[j*8 + r0][kf*8 + c0 + 4];
                mma8(Sv[j], aQ[kf], b0, b1);
            }
        }

        // bias gather + mask + row max
        float mx0 = -1e30f, mx1 = -1e30f;
        #pragma unroll
        for (int j = 0; j < 16; j++) {
            int col = k0 + j*8 + c0*2;
            int2 ia = *(const int2*)(dist_idx + (size_t)qA*S_ + col);
            int2 ib = *(const int2*)(dist_idx + (size_t)qB*S_ + col);
            float2 mk = *(const float2*)&sm.msk[col];
            Sv[j][0] += sm.distCol[ia.x] + mk.x;
            Sv[j][1] += sm.distCol[ia.y] + mk.y;
            Sv[j][2] += sm.distCol[ib.x] + mk.x;
            Sv[j][3] += sm.distCol[ib.y] + mk.y;
            mx0 = fmaxf(mx0, fmaxf(Sv[j][0], Sv[j][1]));
            mx1 = fmaxf(mx1, fmaxf(Sv[j][2], Sv[j][3]));
        }
        mx0 = fmaxf(mx0, __shfl_xor_sync(0xffffffffu, mx0, 1));
        mx0 = fmaxf(mx0, __shfl_xor_sync(0xffffffffu, mx0, 2));
        mx1 = fmaxf(mx1, __shfl_xor_sync(0xffffffffu, mx1, 1));
        mx1 = fmaxf(mx1, __shfl_xor_sync(0xffffffffu, mx1, 2));

        const float mA2 = fmaxf(mA, mx0), mB2 = fmaxf(mB, mx1);
        const float sc0 = __expf(mA - mA2), sc1 = __expf(mB - mB2);

        // P = exp(S - m), write tf32 to smem; accumulate row sums
        float s0 = 0.f, s1 = 0.f;
        #pragma unroll
        for (int j = 0; j < 16; j++) {
            float p0 = __expf(Sv[j][0] - mA2);
            float p1 = __expf(Sv[j][1] - mA2);
            float p2 = __expf(Sv[j][2] - mB2);
            float p3 = __expf(Sv[j][3] - mB2);
            s0 += p0 + p1; s1 += p2 + p3;
            *(uint2*)&sm.Ps[prA][j*8 + c0*2] = make_uint2(f2tf(p0), f2tf(p1));
            *(uint2*)&sm.Ps[prB][j*8 + c0*2] = make_uint2(f2tf(p2), f2tf(p3));
        }
        s0 += __shfl_xor_sync(0xffffffffu, s0, 1);
        s0 += __shfl_xor_sync(0xffffffffu, s0, 2);
        s1 += __shfl_xor_sync(0xffffffffu, s1, 1);
        s1 += __shfl_xor_sync(0xffffffffu, s1, 2);
        lA = lA*sc0 + s0; lB = lB*sc1 + s1;
        mA = mA2; mB = mB2;

        #pragma unroll
        for (int jn = 0; jn < 8; jn++) {
            O[jn][0] *= sc0; O[jn][1] *= sc0;
            O[jn][2] *= sc1; O[jn][3] *= sc1;
        }
        __syncwarp();   // Ps is warp-private: warp-level fence is enough

        // O += P V
        #pragma unroll
        for (int kf = 0; kf < 16; kf++) {
            uint32_t aP[4];
            aP[0] = sm.Ps[prA][kf*8 + c0];
            aP[1] = sm.Ps[prB][kf*8 + c0];
            aP[2] = sm.Ps[prA][kf*8 + c0 + 4];
            aP[3] = sm.Ps[prB][kf*8 + c0 + 4];
            #pragma unroll
            for (int jn = 0; jn < 8; jn++) {
                uint32_t b0 = sm.Vt[jn*8 + r0][kf*8 + c0];
                uint32_t b1 = sm.Vt[jn*8 + r0][kf*8 + c0 + 4];
                mma8(O[jn], aP, b0, b1);
            }
        }
    }

    // Normalize and write straight to [B,S,H] output layout
    const float i0 = 1.f/lA, i1 = 1.f/lB;
    #pragma unroll
    for (int jn = 0; jn < 8; jn++) {
        float2 oa = make_float2(O[jn][0]*i0, O[jn][1]*i0);
        float2 ob = make_float2(O[jn][2]*i1, O[jn][3]*i1);
        *(float2*)&out[((size_t)(b*S_ + qA))*H_ + h*DH_ + jn*8 + c0*2] = oa;
        *(float2*)&out[((size_t)(b*S_ + qB))*H_ + h*DH_ + jn*8 + c0*2] = ob;
    }
}

// ---------------------------------------------------------------------------
// Launch. Inputs (metadata order): hidden, attention_mask, distance_idx,
// Wq, bq, Wk, bk, Wv, bv, dist_emb. Output: float32 [B,S,H].
// ---------------------------------------------------------------------------
extern "C" void kernel_launch(void* const* d_in, const int* in_sizes, int n_in,
                              void* d_out, int out_size)
{
    const float* hidden   = (const float*)d_in[0];
    const float* mask     = (const float*)d_in[1];
    const int*   dist_idx = (const int*)  d_in[2];
    const float* Wq       = (const float*)d_in[3];
    const float* bq       = (const float*)d_in[4];
    const float* Wk       = (const float*)d_in[5];
    const float* bk       = (const float*)d_in[6];
    const float* Wv       = (const float*)d_in[7];
    const float* bv       = (const float*)d_in[8];
    const float* dist_emb = (const float*)d_in[9];
    float* out = (float*)d_out;

    cudaFuncSetAttribute(flash_kernel,
                         cudaFuncAttributeMaxDynamicSharedMemorySize,
                         (int)sizeof(FlashSmem));

    qkv_kernel<<<dim3(H_/128, (B_*S_)/128, 3), 256>>>(hidden, Wq, bq, Wk, bk, Wv, bv);
    flash_kernel<<<dim3(S_/128, BH_), 256, sizeof(FlashSmem)>>>(
        dist_idx, dist_emb, mask, out);
}